// round 1
// baseline (speedup 1.0000x reference)
#include <cuda_runtime.h>
#include <cstdint>

// Problem constants (fixed by the reference)
#define NSLOT 1048576u      // N
#define WDIM  64            // W
#define RHEADS 4            // R
#define EPSF  1e-8f

#define HIST_BUCKETS 8192
#define HIST_SHIFT   19     // bucket = float_bits(usage) >> 19
#define SORT_CAP     8192   // max gathered candidates (power of two for bitonic)
#define KSEL         512    // minimum number of smallest elements to gather

#define MAIN_BLOCKS  (NSLOT / 8)   // 8 warps (rows) per 256-thread block = 131072
#define EXP_BLOCKS   (NSLOT / 256) // 4096

// ---------------- scratch (device globals; no allocations allowed) ------------
__device__ float              g_partial_max[MAIN_BLOCKS];
__device__ float              g_partial_sum[EXP_BLOCKS];
__device__ unsigned           g_hist[HIST_BUCKETS];
__device__ float              g_max;
__device__ float              g_inv_sum;
__device__ unsigned           g_thresh;   // gathered iff float_bits(usage) < g_thresh
__device__ unsigned           g_count;
__device__ unsigned long long g_pairs[SORT_CAP];
__device__ float              g_scale;    // beta / max(||key||, eps)

// ---------------- helpers ------------------------------------------------------
__device__ __forceinline__ float warp_sum(float v) {
    #pragma unroll
    for (int o = 16; o; o >>= 1) v += __shfl_xor_sync(0xffffffffu, v, o);
    return v;
}
__device__ __forceinline__ float warp_max(float v) {
    #pragma unroll
    for (int o = 16; o; o >>= 1) v = fmaxf(v, __shfl_xor_sync(0xffffffffu, v, o));
    return v;
}

// ---------------- kernels ------------------------------------------------------

__global__ void k_zero() {
    for (int i = threadIdx.x; i < HIST_BUCKETS; i += 1024) g_hist[i] = 0u;
    if (threadIdx.x == 0) g_count = 0u;
}

__global__ void k_prep(const float* __restrict__ key, const float* __restrict__ beta) {
    int l = threadIdx.x;  // 32 threads
    float a = key[l], b = key[l + 32];
    float s = warp_sum(a * a + b * b);
    if (l == 0) {
        float kn = fmaxf(sqrtf(s), EPSF);
        g_scale = beta[0] / kn;
    }
}

// Fused pass: per-row cosine numerator/denominator, retention, usage, hist, blockmax.
// Writes: out[0..N) = sim*beta (scratch), out[N..2N) = retention,
//         out[2N..3N) = usage, out[3N..4N) = 0 (allocation init)
__global__ void __launch_bounds__(256) k_main(
    const float* __restrict__ mem, const float* __restrict__ key,
    const float* __restrict__ fg,  const float* __restrict__ rw,
    const float* __restrict__ pu,  const float* __restrict__ ww,
    float* __restrict__ out)
{
    const int warp = threadIdx.x >> 5, lane = threadIdx.x & 31;
    const unsigned row = blockIdx.x * 8u + (unsigned)warp;

    const float2 m2 = reinterpret_cast<const float2*>(mem + (size_t)row * WDIM)[lane];
    const float2 k2 = reinterpret_cast<const float2*>(key)[lane];

    float dot = warp_sum(m2.x * k2.x + m2.y * k2.y);
    float nrm = warp_sum(m2.x * m2.x + m2.y * m2.y);

    __shared__ float smax[8];
    if (lane == 0) {
        float rn  = fmaxf(sqrtf(nrm), EPSF);
        float sim = dot * g_scale / rn;           // sim * beta
        out[row] = sim;
        smax[warp] = sim;

        float4 r4 = reinterpret_cast<const float4*>(rw)[row];
        float ret = (1.0f - r4.x * fg[0]) * (1.0f - r4.y * fg[1])
                  * (1.0f - r4.z * fg[2]) * (1.0f - r4.w * fg[3]);
        out[NSLOT + row] = ret;

        float p = pu[row], w = ww[row];
        float u = (p + w - p * w) * ret;
        out[2u * NSLOT + row] = u;
        out[3u * NSLOT + row] = 0.0f;

        unsigned b = __float_as_uint(u) >> HIST_SHIFT;
        if (b >= HIST_BUCKETS) b = HIST_BUCKETS - 1;
        atomicAdd(&g_hist[b], 1u);
    }
    __syncthreads();
    if (threadIdx.x == 0) {
        float m = smax[0];
        #pragma unroll
        for (int i = 1; i < 8; i++) m = fmaxf(m, smax[i]);
        g_partial_max[blockIdx.x] = m;
    }
}

__global__ void k_rmax() {
    float m = -3.4e38f;
    for (int i = threadIdx.x; i < MAIN_BLOCKS; i += 1024)
        m = fmaxf(m, g_partial_max[i]);
    m = warp_max(m);
    __shared__ float sm[32];
    int lane = threadIdx.x & 31, warp = threadIdx.x >> 5;
    if (lane == 0) sm[warp] = m;
    __syncthreads();
    if (threadIdx.x < 32) {
        float v = sm[lane];
        v = warp_max(v);
        if (lane == 0) g_max = v;
    }
}

// Pick threshold key so that the gathered set contains the KSEL smallest usages
// (capped at SORT_CAP).
__global__ void k_select() {
    __shared__ unsigned tsum[1024];
    __shared__ int sT1, sT2;
    const int t = threadIdx.x;
    unsigned local[8]; unsigned s = 0;
    #pragma unroll
    for (int i = 0; i < 8; i++) { local[i] = g_hist[t * 8 + i]; s += local[i]; }
    tsum[t] = s;
    if (t == 0) { sT1 = HIST_BUCKETS - 1; sT2 = 0x7fffffff; }
    __syncthreads();
    // inclusive Hillis-Steele scan over tsum
    for (int off = 1; off < 1024; off <<= 1) {
        unsigned v = (t >= off) ? tsum[t - off] : 0u;
        __syncthreads();
        tsum[t] += v;
        __syncthreads();
    }
    unsigned cum = (t == 0) ? 0u : tsum[t - 1];   // exclusive base
    #pragma unroll
    for (int i = 0; i < 8; i++) {
        cum += local[i];
        int b = t * 8 + i;
        if (cum >= KSEL)      atomicMin(&sT1, b);  // first bucket reaching KSEL
        if (cum > SORT_CAP)   atomicMin(&sT2, b);  // first bucket overflowing cap
    }
    __syncthreads();
    if (t == 0) {
        int T = sT1;
        if (sT2 != 0x7fffffff && sT2 - 1 < T) T = sT2 - 1;
        if (T < 0) T = 0;
        g_thresh = ((unsigned)(T + 1)) << HIST_SHIFT;
    }
}

// Fused: exp(sim - max) in-place + block partial sums + gather smallest usages.
__global__ void __launch_bounds__(256) k_expgather(float* __restrict__ out) {
    const unsigned i = blockIdx.x * 256u + threadIdx.x;
    float e = expf(out[i] - g_max);
    out[i] = e;

    float s = warp_sum(e);
    __shared__ float ss[8];
    int lane = threadIdx.x & 31, warp = threadIdx.x >> 5;
    if (lane == 0) ss[warp] = s;
    __syncthreads();
    if (threadIdx.x == 0) {
        float tot = ss[0];
        #pragma unroll
        for (int j = 1; j < 8; j++) tot += ss[j];
        g_partial_sum[blockIdx.x] = tot;
    }

    float u = out[2u * NSLOT + i];
    if (__float_as_uint(u) < g_thresh) {
        unsigned pos = atomicAdd(&g_count, 1u);
        if (pos < SORT_CAP)
            g_pairs[pos] = ((unsigned long long)__float_as_uint(u) << 32) | (unsigned long long)i;
    }
}

__global__ void k_rsum() {
    float s = 0.0f;
    for (int i = threadIdx.x; i < EXP_BLOCKS; i += 1024)
        s += g_partial_sum[i];
    s = warp_sum(s);
    __shared__ float sm[32];
    int lane = threadIdx.x & 31, warp = threadIdx.x >> 5;
    if (lane == 0) sm[warp] = s;
    __syncthreads();
    if (threadIdx.x < 32) {
        float v = sm[lane];
        v = warp_sum(v);
        if (lane == 0) g_inv_sum = 1.0f / v;
    }
}

__global__ void __launch_bounds__(256) k_norm(float* __restrict__ out) {
    const unsigned i = blockIdx.x * 256u + threadIdx.x;
    out[i] *= g_inv_sum;
}

// Single block: bitonic sort the gathered (usage_bits:index) pairs (stable,
// matching jnp stable argsort), then serial cumprod with early exit.
__global__ void k_sortalloc(float* __restrict__ out) {
    extern __shared__ unsigned long long sp[];
    const unsigned count = min(g_count, (unsigned)SORT_CAP);
    const int t = threadIdx.x;
    for (int i = t; i < SORT_CAP; i += 1024)
        sp[i] = (i < (int)count) ? g_pairs[i] : 0xFFFFFFFFFFFFFFFFull;
    __syncthreads();

    for (unsigned k = 2; k <= SORT_CAP; k <<= 1) {
        for (unsigned j = k >> 1; j > 0; j >>= 1) {
            for (unsigned i = t; i < SORT_CAP; i += 1024) {
                unsigned ixj = i ^ j;
                if (ixj > i) {
                    bool up = ((i & k) == 0);
                    unsigned long long a = sp[i], b = sp[ixj];
                    if ((a > b) == up) { sp[i] = b; sp[ixj] = a; }
                }
            }
            __syncthreads();
        }
    }

    if (t == 0) {
        // alloc_sorted[0] = 1 - s[0];  alloc_sorted[j] = (1 - s[j-1]) * prod_{i<j} s[i]
        float prod = 1.0f, prev = 0.0f;
        for (unsigned j = 0; j < count; j++) {
            unsigned long long p = sp[j];
            float   sv  = __uint_as_float((unsigned)(p >> 32));
            unsigned idx = (unsigned)(p & 0xFFFFFFFFull);
            float a = (j == 0) ? (1.0f - sv) : (1.0f - prev) * prod;
            out[3u * NSLOT + idx] = a;
            prod *= sv;
            prev  = sv;
            if (prod == 0.0f) break;   // all remaining allocations are exactly 0
        }
    }
}

// ---------------- launch --------------------------------------------------------
extern "C" void kernel_launch(void* const* d_in, const int* in_sizes, int n_in,
                              void* d_out, int out_size)
{
    const float* key  = (const float*)d_in[0];  // desired_content (64)
    const float* mem  = (const float*)d_in[1];  // memory (N*W)
    const float* beta = (const float*)d_in[2];  // key_strength (1)
    const float* fg   = (const float*)d_in[3];  // free_gate (4)
    const float* rw   = (const float*)d_in[4];  // read_weighting (N*4)
    const float* pu   = (const float*)d_in[5];  // previous_usage (N)
    const float* ww   = (const float*)d_in[6];  // write_weighting (N)
    float* out = (float*)d_out;                 // (4, N) float32

    cudaFuncSetAttribute(k_sortalloc, cudaFuncAttributeMaxDynamicSharedMemorySize,
                         SORT_CAP * (int)sizeof(unsigned long long));

    k_zero      <<<1, 1024>>>();
    k_prep      <<<1, 32>>>(key, beta);
    k_main      <<<MAIN_BLOCKS, 256>>>(mem, key, fg, rw, pu, ww, out);
    k_rmax      <<<1, 1024>>>();
    k_select    <<<1, 1024>>>();
    k_expgather <<<EXP_BLOCKS, 256>>>(out);
    k_rsum      <<<1, 1024>>>();
    k_norm      <<<EXP_BLOCKS, 256>>>(out);
    k_sortalloc <<<1, 1024, SORT_CAP * (int)sizeof(unsigned long long)>>>(out);
}

// round 2
// speedup vs baseline: 2.2887x; 2.2887x over previous
#include <cuda_runtime.h>
#include <cstdint>

// Problem constants (fixed by the reference)
#define NSLOT 1048576u      // N
#define WDIM  64            // W
#define EPSF  1e-8f

#define HIST_BUCKETS 8192
#define HIST_SHIFT   19     // bucket = float_bits(usage) >> 19 (usage in [0,1] -> bucket < 2033)
#define SORT_CAP     8192   // max gathered candidates
#define KSEL         512    // minimum number of smallest elements to gather

#define MAIN_BLOCKS  (NSLOT / 256)   // 4096 blocks, thread-per-row

// ---------------- scratch (device globals; no allocations allowed) ------------
__device__ float              g_partial_sum[MAIN_BLOCKS];
__device__ unsigned           g_hist[HIST_BUCKETS];
__device__ float              g_inv_sum;
__device__ unsigned           g_thresh;   // gathered iff float_bits(usage) < g_thresh
__device__ unsigned           g_count;
__device__ unsigned long long g_pairs[SORT_CAP];
__device__ float              g_scale;    // beta / max(||key||, eps)
__device__ float              g_beta;     // softmax shift (sim*beta <= beta)

// ---------------- helpers ------------------------------------------------------
__device__ __forceinline__ float warp_sum(float v) {
    #pragma unroll
    for (int o = 16; o; o >>= 1) v += __shfl_xor_sync(0xffffffffu, v, o);
    return v;
}

// ---------------- kernels ------------------------------------------------------

// 1 block, 256 threads: zero hist/count, compute key norm scale + shift.
__global__ void k_prep(const float* __restrict__ key, const float* __restrict__ beta) {
    const int t = threadIdx.x;
    #pragma unroll
    for (int i = 0; i < HIST_BUCKETS / 256; i++) g_hist[t + i * 256] = 0u;
    if (t == 0) g_count = 0u;
    if (t < 32) {
        float a = key[t], b = key[t + 32];
        float s = warp_sum(a * a + b * b);
        if (t == 0) {
            float kn = fmaxf(sqrtf(s), EPSF);
            float bv = beta[0];
            g_scale = bv / kn;
            g_beta  = bv;
        }
    }
}

// Fused main pass, thread-per-row:
//   out[0..N)   = exp(sim*beta - beta)   (unnormalized content weighting)
//   out[N..2N)  = retention
//   out[2N..3N) = usage
//   out[3N..4N) = 0                       (allocation init)
// plus histogram of usage bits and per-block partial sums of e.
__global__ void __launch_bounds__(256) k_main(
    const float* __restrict__ mem, const float* __restrict__ key,
    const float* __restrict__ fg,  const float* __restrict__ rw,
    const float* __restrict__ pu,  const float* __restrict__ ww,
    float* __restrict__ out)
{
    __shared__ float4 skey[16];
    __shared__ float  ssum[8];
    const int t = threadIdx.x;
    if (t < 16) skey[t] = reinterpret_cast<const float4*>(key)[t];
    __syncthreads();

    const unsigned i = blockIdx.x * 256u + (unsigned)t;
    const float4* m4 = reinterpret_cast<const float4*>(mem) + (size_t)i * 16;

    // dot & norm with dual accumulators to break dependency chains
    float d0 = 0.f, d1 = 0.f, n0 = 0.f, n1 = 0.f;
    #pragma unroll
    for (int j = 0; j < 16; j += 2) {
        float4 v0 = m4[j], v1 = m4[j + 1];
        float4 k0 = skey[j], k1 = skey[j + 1];
        d0 += v0.x * k0.x + v0.y * k0.y + v0.z * k0.z + v0.w * k0.w;
        n0 += v0.x * v0.x + v0.y * v0.y + v0.z * v0.z + v0.w * v0.w;
        d1 += v1.x * k1.x + v1.y * k1.y + v1.z * k1.z + v1.w * k1.w;
        n1 += v1.x * v1.x + v1.y * v1.y + v1.z * v1.z + v1.w * v1.w;
    }
    float dot = d0 + d1, nrm = n0 + n1;

    float rn = fmaxf(sqrtf(nrm), EPSF);
    float e  = expf(dot * g_scale / rn - g_beta);   // exp(sim*beta - beta), always in (0,1]
    out[i] = e;

    // retention / usage
    float4 fg4 = *reinterpret_cast<const float4*>(fg);
    float4 r4  = reinterpret_cast<const float4*>(rw)[i];
    float ret = (1.0f - r4.x * fg4.x) * (1.0f - r4.y * fg4.y)
              * (1.0f - r4.z * fg4.z) * (1.0f - r4.w * fg4.w);
    out[NSLOT + i] = ret;

    float p = pu[i], w = ww[i];
    float u = (p + w - p * w) * ret;
    out[2u * NSLOT + i] = u;
    out[3u * NSLOT + i] = 0.0f;

    unsigned b = __float_as_uint(u) >> HIST_SHIFT;
    if (b >= HIST_BUCKETS) b = HIST_BUCKETS - 1;
    atomicAdd(&g_hist[b], 1u);

    // block partial sum of e
    float s = warp_sum(e);
    int lane = t & 31, warp = t >> 5;
    if (lane == 0) ssum[warp] = s;
    __syncthreads();
    if (t == 0) {
        float tot = ssum[0];
        #pragma unroll
        for (int j = 1; j < 8; j++) tot += ssum[j];
        g_partial_sum[blockIdx.x] = tot;
    }
}

// 1 block, 1024 threads: reduce partial sums -> 1/sum, and pick gather threshold
// from histogram (first bucket covering >= KSEL smallest, capped at SORT_CAP).
__global__ void k_mid() {
    const int t = threadIdx.x;
    __shared__ float sm[32];

    // ---- sum reduce
    float s = 0.0f;
    #pragma unroll
    for (int j = 0; j < MAIN_BLOCKS / 1024; j++) s += g_partial_sum[t + j * 1024];
    s = warp_sum(s);
    int lane = t & 31, warp = t >> 5;
    if (lane == 0) sm[warp] = s;
    __syncthreads();
    if (t < 32) {
        float v = sm[t];
        v = warp_sum(v);
        if (t == 0) g_inv_sum = 1.0f / v;
    }

    // ---- histogram threshold selection
    __shared__ unsigned tsum[1024];
    __shared__ int sT1, sT2;
    unsigned local[HIST_BUCKETS / 1024]; unsigned acc = 0;
    #pragma unroll
    for (int j = 0; j < HIST_BUCKETS / 1024; j++) { local[j] = g_hist[t * (HIST_BUCKETS / 1024) + j]; acc += local[j]; }
    tsum[t] = acc;
    if (t == 0) { sT1 = HIST_BUCKETS - 1; sT2 = 0x7fffffff; }
    __syncthreads();
    for (int off = 1; off < 1024; off <<= 1) {
        unsigned v = (t >= off) ? tsum[t - off] : 0u;
        __syncthreads();
        tsum[t] += v;
        __syncthreads();
    }
    unsigned cum = (t == 0) ? 0u : tsum[t - 1];
    #pragma unroll
    for (int j = 0; j < HIST_BUCKETS / 1024; j++) {
        cum += local[j];
        int b = t * (HIST_BUCKETS / 1024) + j;
        if (cum >= KSEL)    atomicMin(&sT1, b);
        if (cum > SORT_CAP) atomicMin(&sT2, b);
    }
    __syncthreads();
    if (t == 0) {
        int T = sT1;
        if (sT2 != 0x7fffffff && sT2 - 1 < T) T = sT2 - 1;
        if (T < 0) T = 0;
        g_thresh = ((unsigned)(T + 1)) << HIST_SHIFT;
    }
}

// Normalize content weighting + gather smallest usages in one pass.
__global__ void __launch_bounds__(256) k_pass2(float* __restrict__ out) {
    const unsigned i = blockIdx.x * 256u + threadIdx.x;
    out[i] *= g_inv_sum;
    float u = out[2u * NSLOT + i];
    if (__float_as_uint(u) < g_thresh) {
        unsigned pos = atomicAdd(&g_count, 1u);
        if (pos < SORT_CAP)
            g_pairs[pos] = ((unsigned long long)__float_as_uint(u) << 32) | (unsigned long long)i;
    }
}

// Single block: bitonic sort (dynamic power-of-two size) of (usage_bits:index)
// pairs -- stable order matches jnp argsort -- then serial cumprod w/ early exit.
__global__ void k_sortalloc(float* __restrict__ out) {
    extern __shared__ unsigned long long sp[];
    const unsigned count = min(g_count, (unsigned)SORT_CAP);
    unsigned n = 2;
    while (n < count) n <<= 1;               // next pow2 >= count (>=2)

    const int t = threadIdx.x;
    for (unsigned i = t; i < n; i += 1024)
        sp[i] = (i < count) ? g_pairs[i] : 0xFFFFFFFFFFFFFFFFull;
    __syncthreads();

    for (unsigned k = 2; k <= n; k <<= 1) {
        for (unsigned j = k >> 1; j > 0; j >>= 1) {
            for (unsigned i = t; i < n; i += 1024) {
                unsigned ixj = i ^ j;
                if (ixj > i) {
                    bool up = ((i & k) == 0);
                    unsigned long long a = sp[i], b = sp[ixj];
                    if ((a > b) == up) { sp[i] = b; sp[ixj] = a; }
                }
            }
            __syncthreads();
        }
    }

    if (t == 0) {
        // alloc_sorted[0] = 1 - s[0];  alloc_sorted[j] = (1 - s[j-1]) * prod_{i<j} s[i]
        float prod = 1.0f, prev = 0.0f;
        for (unsigned j = 0; j < count; j++) {
            unsigned long long p = sp[j];
            float    sv  = __uint_as_float((unsigned)(p >> 32));
            unsigned idx = (unsigned)(p & 0xFFFFFFFFull);
            float a = (j == 0) ? (1.0f - sv) : (1.0f - prev) * prod;
            out[3u * NSLOT + idx] = a;
            prod *= sv;
            prev  = sv;
            if (prod == 0.0f) break;   // all remaining allocations are exactly 0
        }
    }
}

// ---------------- launch --------------------------------------------------------
extern "C" void kernel_launch(void* const* d_in, const int* in_sizes, int n_in,
                              void* d_out, int out_size)
{
    const float* key  = (const float*)d_in[0];  // desired_content (64)
    const float* mem  = (const float*)d_in[1];  // memory (N*W)
    const float* beta = (const float*)d_in[2];  // key_strength (1)
    const float* fg   = (const float*)d_in[3];  // free_gate (4)
    const float* rw   = (const float*)d_in[4];  // read_weighting (N*4)
    const float* pu   = (const float*)d_in[5];  // previous_usage (N)
    const float* ww   = (const float*)d_in[6];  // write_weighting (N)
    float* out = (float*)d_out;                 // (4, N) float32

    cudaFuncSetAttribute(k_sortalloc, cudaFuncAttributeMaxDynamicSharedMemorySize,
                         SORT_CAP * (int)sizeof(unsigned long long));

    k_prep      <<<1, 256>>>(key, beta);
    k_main      <<<MAIN_BLOCKS, 256>>>(mem, key, fg, rw, pu, ww, out);
    k_mid       <<<1, 1024>>>();
    k_pass2     <<<MAIN_BLOCKS, 256>>>(out);
    k_sortalloc <<<1, 1024, SORT_CAP * (int)sizeof(unsigned long long)>>>(out);
}

// round 3
// speedup vs baseline: 3.3128x; 1.4474x over previous
#include <cuda_runtime.h>
#include <cstdint>

// Problem constants (fixed by the reference)
#define NSLOT 1048576u      // N
#define WDIM  64            // W
#define EPSF  1e-8f

#define HIST_BUCKETS 2048   // u in [0,1) -> bucket = float_bits(u)>>19 in [0, 2032]
#define HIST_SHIFT   19
#define SORT_CAP     8192   // max gathered candidates
#define KSEL         256    // minimum number of smallest elements to gather

#define TILE_ROWS    256
#define MAIN_BLOCKS  (NSLOT / TILE_ROWS)   // 4096 blocks, one 256-row tile each
#define PITCH        17                     // float4 pitch: conflict-free smem

// ---------------- scratch (device globals; no allocations allowed) ------------
__device__ float              g_partial_sum[MAIN_BLOCKS];
__device__ unsigned           g_hist[HIST_BUCKETS];
__device__ float              g_inv_sum;
__device__ unsigned           g_thresh;   // gathered iff float_bits(usage) < g_thresh
__device__ unsigned           g_count;
__device__ unsigned long long g_pairs[SORT_CAP];
__device__ float              g_scale;    // beta / max(||key||, eps)
__device__ float              g_beta;     // softmax shift (sim*beta <= beta)

// ---------------- helpers ------------------------------------------------------
__device__ __forceinline__ float warp_sum(float v) {
    #pragma unroll
    for (int o = 16; o; o >>= 1) v += __shfl_xor_sync(0xffffffffu, v, o);
    return v;
}

// ---------------- kernels ------------------------------------------------------

// 1 block, 256 threads: zero hist/count, compute key norm scale + shift.
__global__ void k_prep(const float* __restrict__ key, const float* __restrict__ beta) {
    const int t = threadIdx.x;
    #pragma unroll
    for (int i = 0; i < HIST_BUCKETS / 256; i++) g_hist[t + i * 256] = 0u;
    if (t == 0) g_count = 0u;
    if (t < 32) {
        float a = key[t], b = key[t + 32];
        float s = warp_sum(a * a + b * b);
        if (t == 0) {
            float kn = fmaxf(sqrtf(s), EPSF);
            float bv = beta[0];
            g_scale = bv / kn;
            g_beta  = bv;
        }
    }
}

// Fused main pass. One block = one 256-row tile of `memory`, staged through
// shared memory with coalesced global loads and conflict-free smem layout.
//   out[0..N)   = exp(sim*beta - beta)   (unnormalized content weighting)
//   out[N..2N)  = retention
//   out[2N..3N) = usage
//   out[3N..4N) = 0                       (allocation init)
// plus usage histogram (warp-aggregated atomics) and per-block sums of e.
__global__ void __launch_bounds__(256) k_main(
    const float* __restrict__ mem, const float* __restrict__ key,
    const float* __restrict__ fg,  const float* __restrict__ rw,
    const float* __restrict__ pu,  const float* __restrict__ ww,
    float* __restrict__ out)
{
    extern __shared__ float4 s[];              // [TILE_ROWS * PITCH] float4
    __shared__ float4 skey[16];
    __shared__ float  ssum[8];

    const int t = threadIdx.x;
    if (t < 16) skey[t] = reinterpret_cast<const float4*>(key)[t];

    // --- coalesced load of 256 rows x 64 floats (4096 float4) into padded smem
    const float4* gmem4 = reinterpret_cast<const float4*>(mem) + (size_t)blockIdx.x * (TILE_ROWS * 16);
    #pragma unroll
    for (int k = 0; k < 16; k++) {
        int f = t + 256 * k;                   // flat float4 index in tile
        float4 v = gmem4[f];
        s[(f >> 4) * PITCH + (f & 15)] = v;    // row-major, pitch 17
    }
    __syncthreads();

    // --- per-thread row reduction from smem (conflict-free: 17 mod 8 == 1)
    const float4* row = s + t * PITCH;
    float d0 = 0.f, d1 = 0.f, n0 = 0.f, n1 = 0.f;
    #pragma unroll
    for (int c = 0; c < 16; c += 2) {
        float4 v0 = row[c],    k0 = skey[c];
        float4 v1 = row[c + 1], k1 = skey[c + 1];
        d0 += v0.x * k0.x + v0.y * k0.y + v0.z * k0.z + v0.w * k0.w;
        n0 += v0.x * v0.x + v0.y * v0.y + v0.z * v0.z + v0.w * v0.w;
        d1 += v1.x * k1.x + v1.y * k1.y + v1.z * k1.z + v1.w * k1.w;
        n1 += v1.x * v1.x + v1.y * v1.y + v1.z * v1.z + v1.w * v1.w;
    }
    float dot = d0 + d1, nrm = n0 + n1;

    const unsigned i = blockIdx.x * (unsigned)TILE_ROWS + (unsigned)t;

    float rn = fmaxf(sqrtf(nrm), EPSF);
    float e  = expf(dot * g_scale / rn - g_beta);   // exp(sim*beta - beta) in (0,1]
    out[i] = e;

    // retention / usage (all coalesced, thread-per-row)
    float4 fg4 = *reinterpret_cast<const float4*>(fg);
    float4 r4  = reinterpret_cast<const float4*>(rw)[i];
    float ret = (1.0f - r4.x * fg4.x) * (1.0f - r4.y * fg4.y)
              * (1.0f - r4.z * fg4.z) * (1.0f - r4.w * fg4.w);
    out[NSLOT + i] = ret;

    float p = pu[i], w = ww[i];
    float u = (p + w - p * w) * ret;
    out[2u * NSLOT + i] = u;
    out[3u * NSLOT + i] = 0.0f;

    // histogram with warp aggregation (merge lanes hitting the same bucket)
    unsigned b = __float_as_uint(u) >> HIST_SHIFT;
    if (b >= HIST_BUCKETS) b = HIST_BUCKETS - 1;
    unsigned peers = __match_any_sync(0xffffffffu, b);
    int leader = __ffs(peers) - 1;
    if ((t & 31) == leader) atomicAdd(&g_hist[b], (unsigned)__popc(peers));

    // block partial sum of e
    float sum = warp_sum(e);
    int lane = t & 31, warp = t >> 5;
    if (lane == 0) ssum[warp] = sum;
    __syncthreads();
    if (t == 0) {
        float tot = ssum[0];
        #pragma unroll
        for (int j = 1; j < 8; j++) tot += ssum[j];
        g_partial_sum[blockIdx.x] = tot;
    }
}

// 1 block, 1024 threads: reduce partial sums -> 1/sum; pick gather threshold
// from histogram (first bucket covering >= KSEL smallest, capped at SORT_CAP).
__global__ void k_mid() {
    const int t = threadIdx.x;
    __shared__ float sm[32];

    // ---- sum reduce
    float s = 0.0f;
    #pragma unroll
    for (int j = 0; j < MAIN_BLOCKS / 1024; j++) s += g_partial_sum[t + j * 1024];
    s = warp_sum(s);
    int lane = t & 31, warp = t >> 5;
    if (lane == 0) sm[warp] = s;
    __syncthreads();
    if (t < 32) {
        float v = sm[t];
        v = warp_sum(v);
        if (t == 0) g_inv_sum = 1.0f / v;
    }

    // ---- histogram threshold selection (2048 buckets, 2 per thread)
    __shared__ unsigned tsum[1024];
    __shared__ int sT1, sT2;
    unsigned l0 = g_hist[t * 2], l1 = g_hist[t * 2 + 1];
    tsum[t] = l0 + l1;
    if (t == 0) { sT1 = HIST_BUCKETS - 1; sT2 = 0x7fffffff; }
    __syncthreads();
    for (int off = 1; off < 1024; off <<= 1) {
        unsigned v = (t >= off) ? tsum[t - off] : 0u;
        __syncthreads();
        tsum[t] += v;
        __syncthreads();
    }
    unsigned cum = (t == 0) ? 0u : tsum[t - 1];
    cum += l0;
    if (cum >= KSEL)    atomicMin(&sT1, t * 2);
    if (cum > SORT_CAP) atomicMin(&sT2, t * 2);
    cum += l1;
    if (cum >= KSEL)    atomicMin(&sT1, t * 2 + 1);
    if (cum > SORT_CAP) atomicMin(&sT2, t * 2 + 1);
    __syncthreads();
    if (t == 0) {
        int T = sT1;
        if (sT2 != 0x7fffffff && sT2 - 1 < T) T = sT2 - 1;
        if (T < 0) T = 0;
        g_thresh = ((unsigned)(T + 1)) << HIST_SHIFT;
    }
}

// Normalize content weighting + gather smallest usages, vectorized float4.
__global__ void __launch_bounds__(256) k_pass2(float* __restrict__ out) {
    const unsigned q = blockIdx.x * 256u + threadIdx.x;     // float4 index
    float4* o4 = reinterpret_cast<float4*>(out);
    float4 e = o4[q];
    float inv = g_inv_sum;
    e.x *= inv; e.y *= inv; e.z *= inv; e.w *= inv;
    o4[q] = e;

    float4 u = o4[(2u * NSLOT) / 4 + q];
    unsigned base = q * 4u;
    const unsigned th = g_thresh;
    #pragma unroll
    for (int c = 0; c < 4; c++) {
        float uv = (c == 0) ? u.x : (c == 1) ? u.y : (c == 2) ? u.z : u.w;
        if (__float_as_uint(uv) < th) {
            unsigned pos = atomicAdd(&g_count, 1u);
            if (pos < SORT_CAP)
                g_pairs[pos] = ((unsigned long long)__float_as_uint(uv) << 32)
                             | (unsigned long long)(base + c);
        }
    }
}

// Single block: bitonic sort (dynamic power-of-two size) of (usage_bits:index)
// pairs -- 64-bit key gives the stable order of jnp argsort -- then serial
// cumprod with early exit once the product underflows to exactly 0.
__global__ void k_sortalloc(float* __restrict__ out) {
    extern __shared__ unsigned long long sp[];
    const unsigned count = min(g_count, (unsigned)SORT_CAP);
    unsigned n = 2;
    while (n < count) n <<= 1;

    const int t = threadIdx.x;
    for (unsigned i = t; i < n; i += 1024)
        sp[i] = (i < count) ? g_pairs[i] : 0xFFFFFFFFFFFFFFFFull;
    __syncthreads();

    for (unsigned k = 2; k <= n; k <<= 1) {
        for (unsigned j = k >> 1; j > 0; j >>= 1) {
            for (unsigned i = t; i < n; i += 1024) {
                unsigned ixj = i ^ j;
                if (ixj > i) {
                    bool up = ((i & k) == 0);
                    unsigned long long a = sp[i], b = sp[ixj];
                    if ((a > b) == up) { sp[i] = b; sp[ixj] = a; }
                }
            }
            __syncthreads();
        }
    }

    if (t == 0) {
        float prod = 1.0f, prev = 0.0f;
        for (unsigned j = 0; j < count; j++) {
            unsigned long long p = sp[j];
            float    sv  = __uint_as_float((unsigned)(p >> 32));
            unsigned idx = (unsigned)(p & 0xFFFFFFFFull);
            float a = (j == 0) ? (1.0f - sv) : (1.0f - prev) * prod;
            out[3u * NSLOT + idx] = a;
            prod *= sv;
            prev  = sv;
            if (prod == 0.0f) break;   // remaining allocations are exactly 0
        }
    }
}

// ---------------- launch --------------------------------------------------------
extern "C" void kernel_launch(void* const* d_in, const int* in_sizes, int n_in,
                              void* d_out, int out_size)
{
    const float* key  = (const float*)d_in[0];  // desired_content (64)
    const float* mem  = (const float*)d_in[1];  // memory (N*W)
    const float* beta = (const float*)d_in[2];  // key_strength (1)
    const float* fg   = (const float*)d_in[3];  // free_gate (4)
    const float* rw   = (const float*)d_in[4];  // read_weighting (N*4)
    const float* pu   = (const float*)d_in[5];  // previous_usage (N)
    const float* ww   = (const float*)d_in[6];  // write_weighting (N)
    float* out = (float*)d_out;                 // (4, N) float32

    const int main_smem = TILE_ROWS * PITCH * (int)sizeof(float4);   // 69,632 B
    cudaFuncSetAttribute(k_main, cudaFuncAttributeMaxDynamicSharedMemorySize, main_smem);
    cudaFuncSetAttribute(k_sortalloc, cudaFuncAttributeMaxDynamicSharedMemorySize,
                         SORT_CAP * (int)sizeof(unsigned long long));

    k_prep      <<<1, 256>>>(key, beta);
    k_main      <<<MAIN_BLOCKS, 256, main_smem>>>(mem, key, fg, rw, pu, ww, out);
    k_mid       <<<1, 1024>>>();
    k_pass2     <<<NSLOT / 1024, 256>>>(out);
    k_sortalloc <<<1, 1024, SORT_CAP * (int)sizeof(unsigned long long)>>>(out);
}